// round 1
// baseline (speedup 1.0000x reference)
#include <cuda_runtime.h>
#include <cstdint>

// Problem constants
#define BB   4
#define C3   256
#define H3   48
#define L3   (H3*H3)          // 2304
#define C2   128
#define H2   96
#define L2n  (H2*H2)          // 9216
#define C1   64
#define H1   192
#define L1n  (H1*H1)          // 36864
#define EPSN 1e-12f

// ---------------- scratch (static device globals; no allocation) -------------
__device__ float g_P[(size_t)BB * L3 * L3];          // [b][lq][lk]  ~85MB
__device__ float g_cl3T[(size_t)BB * L3 * C3];       // [b][pix][c]
__device__ float g_cl2T[(size_t)BB * L2n * C2];
__device__ float g_cl1T[(size_t)BB * L1n * C1];
__device__ float g_sq[2][BB * L3];                    // per-pixel sq-norm: 0=img 1=ref
__device__ float g_nrm[2][BB * L3];                   // patch norms: 0=nq(img) 1=nk(ref)
__device__ int   g_idx[BB * L3];                      // argmax index per query

// ---------------- 1) per-pixel squared norms ---------------------------------
__global__ void sqsum_kernel(const float* __restrict__ img, const float* __restrict__ ref) {
    int l = blockIdx.x * 256 + threadIdx.x;           // 0..2303
    int b = blockIdx.y;
    int which = blockIdx.z;                           // 0=img 1=ref
    const float* src = (which == 0) ? img : ref;
    src += (size_t)b * C3 * L3 + l;
    float s = 0.f;
    #pragma unroll 4
    for (int c = 0; c < C3; c++) {
        float v = src[(size_t)c * L3];
        s += v * v;
    }
    g_sq[which][b * L3 + l] = s;
}

// ---------------- 2) 3x3 box-sum -> patch norm -------------------------------
__global__ void boxnorm_kernel() {
    int l = blockIdx.x * 256 + threadIdx.x;
    int b = blockIdx.y;
    int which = blockIdx.z;
    int y = l / H3, x = l % H3;
    const float* s = &g_sq[which][b * L3];
    float acc = 0.f;
    #pragma unroll
    for (int dy = -1; dy <= 1; dy++) {
        int yy = y + dy;
        if ((unsigned)yy >= H3) continue;
        #pragma unroll
        for (int dx = -1; dx <= 1; dx++) {
            int xx = x + dx;
            if ((unsigned)xx >= H3) continue;
            acc += s[yy * H3 + xx];
        }
    }
    g_nrm[which][b * L3 + l] = fmaxf(sqrtf(acc), EPSN);
}

// ---------------- 3) transpose cl_ref to channel-last ------------------------
// src: [B][C][L] -> dst: [B][L][C].  C,L both multiples of 32.
__global__ void transpose_kernel(const float* __restrict__ src, int C, int L, int sel) {
    float* dst = (sel == 0) ? g_cl3T : (sel == 1) ? g_cl2T : g_cl1T;
    __shared__ float tile[32][33];
    int l0 = blockIdx.x * 32, c0 = blockIdx.y * 32, b = blockIdx.z;
    const float* s = src + (size_t)b * C * L;
    float* d = dst + (size_t)b * L * C;
    #pragma unroll
    for (int i = threadIdx.y; i < 32; i += 8)
        tile[i][threadIdx.x] = s[(size_t)(c0 + i) * L + l0 + threadIdx.x];
    __syncthreads();
    #pragma unroll
    for (int i = threadIdx.y; i < 32; i += 8)
        d[(size_t)(l0 + i) * C + c0 + threadIdx.x] = tile[threadIdx.x][i];
}

// ---------------- 4) SGEMM: P[b][lq][lk] = sum_c img[c][lq]*ref[c][lk] -------
// A = img (M = lq), B = ref (N = lk), K = 256. 128x128 tile, 8x8 microtile.
__global__ void __launch_bounds__(256, 2) gemm_kernel(const float* __restrict__ img,
                                                      const float* __restrict__ ref) {
    const int b  = blockIdx.z;
    const int m0 = blockIdx.y * 128;
    const int n0 = blockIdx.x * 128;
    const float* A  = img + (size_t)b * C3 * L3;   // [k][m]
    const float* Bm = ref + (size_t)b * C3 * L3;   // [k][n]
    float* Cc = g_P + (size_t)b * L3 * L3;

    __shared__ float As[8][128];
    __shared__ float Bs[8][128];

    int tid = threadIdx.x;
    int lr  = tid >> 5;            // 0..7 (load row)
    int lc4 = (tid & 31) * 4;      // 0..124 (load col, float4)
    int tx  = tid & 15;
    int ty  = tid >> 4;

    float acc[8][8];
    #pragma unroll
    for (int i = 0; i < 8; i++)
        #pragma unroll
        for (int j = 0; j < 8; j++) acc[i][j] = 0.f;

    for (int k0 = 0; k0 < C3; k0 += 8) {
        *(float4*)&As[lr][lc4] = *(const float4*)&A [(size_t)(k0 + lr) * L3 + m0 + lc4];
        *(float4*)&Bs[lr][lc4] = *(const float4*)&Bm[(size_t)(k0 + lr) * L3 + n0 + lc4];
        __syncthreads();
        #pragma unroll
        for (int kk = 0; kk < 8; kk++) {
            float a[8], bv[8];
            *(float4*)&a[0]  = *(float4*)&As[kk][ty * 4];
            *(float4*)&a[4]  = *(float4*)&As[kk][64 + ty * 4];
            *(float4*)&bv[0] = *(float4*)&Bs[kk][tx * 4];
            *(float4*)&bv[4] = *(float4*)&Bs[kk][64 + tx * 4];
            #pragma unroll
            for (int i = 0; i < 8; i++)
                #pragma unroll
                for (int j = 0; j < 8; j++)
                    acc[i][j] += a[i] * bv[j];
        }
        __syncthreads();
    }

    #pragma unroll
    for (int i = 0; i < 8; i++) {
        int m = m0 + ((i < 4) ? (ty * 4 + i) : (64 + ty * 4 + i - 4));
        float* row = Cc + (size_t)m * L3;
        float4 v0 = make_float4(acc[i][0], acc[i][1], acc[i][2], acc[i][3]);
        float4 v1 = make_float4(acc[i][4], acc[i][5], acc[i][6], acc[i][7]);
        *(float4*)&row[n0 + tx * 4]      = v0;
        *(float4*)&row[n0 + 64 + tx * 4] = v1;
    }
}

// ---------------- 5) shifted-sum + max/argmax over lk ------------------------
// rel(lk,lq) = (sum over 9 diagonal shifts of P) / (nk[lk]*nq[lq]); take max over lk.
__global__ void maxarg_kernel(float* __restrict__ outS) {
    int b = blockIdx.y, lq = blockIdx.x;
    int yq = lq / H3, xq = lq % H3;
    const float* base = g_P + (size_t)b * L3 * L3;

    int  rowOff[9];
    bool qv[9];
    #pragma unroll
    for (int t = 0; t < 9; t++) {
        int di = t / 3 - 1, dj = t % 3 - 1;
        int y2 = yq + di, x2 = xq + dj;
        bool v = ((unsigned)y2 < H3) && ((unsigned)x2 < H3);
        qv[t] = v;
        int d = di * H3 + dj;
        rowOff[t] = v ? (lq + d) * L3 + d : 0;
    }
    const float* nk = &g_nrm[1][b * L3];

    float best = -1e30f; int bi = 0;
    for (int lk = threadIdx.x; lk < L3; lk += 256) {
        int yk = lk / H3, xk = lk % H3;
        float s = 0.f;
        #pragma unroll
        for (int t = 0; t < 9; t++) {
            int di = t / 3 - 1, dj = t % 3 - 1;
            if (qv[t] && ((unsigned)(yk + di) < H3) && ((unsigned)(xk + dj) < H3))
                s += base[rowOff[t] + lk];
        }
        float sc = s / nk[lk];
        if (sc > best) { best = sc; bi = lk; }
    }

    __shared__ float sv[256];
    __shared__ int   si[256];
    sv[threadIdx.x] = best; si[threadIdx.x] = bi;
    __syncthreads();
    for (int st = 128; st > 0; st >>= 1) {
        if (threadIdx.x < st) {
            float o = sv[threadIdx.x + st]; int oi = si[threadIdx.x + st];
            if (o > sv[threadIdx.x] || (o == sv[threadIdx.x] && oi < si[threadIdx.x])) {
                sv[threadIdx.x] = o; si[threadIdx.x] = oi;
            }
        }
        __syncthreads();
    }
    if (threadIdx.x == 0) {
        g_idx[b * L3 + lq] = si[0];
        outS[b * L3 + lq]  = sv[0] / g_nrm[0][b * L3 + lq];
    }
}

// ---------------- 6) fused gather + fold-normalize ---------------------------
// Per output pixel (y,x) at scale s (k=3s,p=s,stride=s): neighbors yq,xq in
// {floor/s -1,0,+1} clipped to [0,48); source coord ys = y + s*(yk-yq).
// out[b][c][y][x] = sum(valid src reads, zero OOB) / (#covering patches).
__global__ void transfer_kernel(float* __restrict__ out, int C, int W, int s, int sel) {
    const float* clT = (sel == 0) ? g_cl3T : (sel == 1) ? g_cl2T : g_cl1T;
    __shared__ float acc[12288];                 // C*W floats == 48KB for all levels
    int b = blockIdx.y, y = blockIdx.x;
    int tid = threadIdx.x;
    int cid  = tid % C;
    int xsub = tid / C;
    int ppp  = 256 / C;                          // pixels handled in parallel

    int tyq = y / s;
    int yqs[3]; int nvy = 0;
    #pragma unroll
    for (int d = -1; d <= 1; d++) {
        int yq = tyq + d;
        if (0 <= yq && yq < H3) yqs[nvy++] = yq;
    }
    const int* idxb = g_idx + b * L3;
    size_t clb = (size_t)b * W * W * C;

    for (int x0 = 0; x0 < W; x0 += ppp) {
        int x = x0 + xsub;
        int txq = x / s;
        float sum = 0.f; int cnt = 0;
        for (int a = 0; a < nvy; a++) {
            int yq = yqs[a];
            #pragma unroll
            for (int d = -1; d <= 1; d++) {
                int xq = txq + d;
                if ((unsigned)xq >= H3) continue;
                cnt++;
                int idx = idxb[yq * H3 + xq];
                int yk = idx / H3, xk = idx % H3;
                int ys = y + s * (yk - yq);
                int xs = x + s * (xk - xq);
                if ((unsigned)ys < (unsigned)W && (unsigned)xs < (unsigned)W)
                    sum += clT[clb + ((size_t)ys * W + xs) * C + cid];
            }
        }
        acc[cid * W + x] = sum / (float)cnt;
    }
    __syncthreads();

    size_t ob = (size_t)b * C * W * W + (size_t)y * W;
    for (int i = tid; i < C * W; i += 256) {
        int c = i / W, x = i % W;
        out[ob + (size_t)c * W * W + x] = acc[i];
    }
}

// ---------------- launch ------------------------------------------------------
extern "C" void kernel_launch(void* const* d_in, const int* in_sizes, int n_in,
                              void* d_out, int out_size) {
    const float* img = (const float*)d_in[0];   // dh_img_lv3 [4,256,48,48]
    const float* ref = (const float*)d_in[1];   // dh_ref_lv3 [4,256,48,48]
    const float* cl1 = (const float*)d_in[2];   // cl_ref_lv1 [4,64,192,192]
    const float* cl2 = (const float*)d_in[3];   // cl_ref_lv2 [4,128,96,96]
    const float* cl3 = (const float*)d_in[4];   // cl_ref_lv3 [4,256,48,48]

    float* outS  = (float*)d_out;               // [4,1,48,48]
    float* outT3 = outS  + BB * L3;             // [4,256,48,48]
    float* outT2 = outT3 + (size_t)BB * C3 * L3;    // [4,128,96,96]
    float* outT1 = outT2 + (size_t)BB * C2 * L2n;   // [4,64,192,192]

    sqsum_kernel  <<<dim3(9, BB, 2), 256>>>(img, ref);
    boxnorm_kernel<<<dim3(9, BB, 2), 256>>>();

    transpose_kernel<<<dim3(L3  / 32, C3 / 32, BB), dim3(32, 8)>>>(cl3, C3, L3,  0);
    transpose_kernel<<<dim3(L2n / 32, C2 / 32, BB), dim3(32, 8)>>>(cl2, C2, L2n, 1);
    transpose_kernel<<<dim3(L1n / 32, C1 / 32, BB), dim3(32, 8)>>>(cl1, C1, L1n, 2);

    gemm_kernel<<<dim3(L3 / 128, L3 / 128, BB), 256>>>(img, ref);

    maxarg_kernel<<<dim3(L3, BB), 256>>>(outS);

    transfer_kernel<<<dim3(H3, BB), 256>>>(outT3, C3, H3, 1, 0);
    transfer_kernel<<<dim3(H2, BB), 256>>>(outT2, C2, H2, 2, 1);
    transfer_kernel<<<dim3(H1, BB), 256>>>(outT1, C1, H1, 4, 2);
}

// round 2
// speedup vs baseline: 1.0574x; 1.0574x over previous
#include <cuda_runtime.h>
#include <cstdint>

// Problem constants
#define BB   4
#define C3   256
#define H3   48
#define L3   (H3*H3)          // 2304
#define C2   128
#define H2   96
#define L2n  (H2*H2)          // 9216
#define C1   64
#define H1   192
#define L1n  (H1*H1)          // 36864
#define EPSN 1e-12f

#define BK 16

// ---------------- scratch (static device globals; no allocation) -------------
__device__ float g_P[(size_t)BB * L3 * L3];          // [b][lq][lk]  ~85MB
__device__ float g_cl3T[(size_t)BB * L3 * C3];       // [b][pix][c]
__device__ float g_cl2T[(size_t)BB * L2n * C2];
__device__ float g_cl1T[(size_t)BB * L1n * C1];
__device__ float g_sq[2][BB * L3];                    // per-pixel sq-norm: 0=img 1=ref
__device__ float g_nrm[2][BB * L3];                   // 0: nq(img) norm, 1: 1/nk(ref)
__device__ int   g_idx[BB * L3];                      // argmax index per query

// ---------------- cp.async helpers -------------------------------------------
__device__ __forceinline__ void cp_async16(uint32_t smem, const void* gmem) {
    asm volatile("cp.async.cg.shared.global [%0], [%1], 16;\n" :: "r"(smem), "l"(gmem));
}
__device__ __forceinline__ void cp_commit() {
    asm volatile("cp.async.commit_group;\n" ::: "memory");
}
__device__ __forceinline__ void cp_wait0() {
    asm volatile("cp.async.wait_group 0;\n" ::: "memory");
}

// ---------------- 1) per-pixel squared norms ---------------------------------
__global__ void sqsum_kernel(const float* __restrict__ img, const float* __restrict__ ref) {
    int l = blockIdx.x * 256 + threadIdx.x;           // 0..2303
    int b = blockIdx.y;
    int which = blockIdx.z;                           // 0=img 1=ref
    const float* src = (which == 0) ? img : ref;
    src += (size_t)b * C3 * L3 + l;
    float s = 0.f;
    #pragma unroll 4
    for (int c = 0; c < C3; c++) {
        float v = src[(size_t)c * L3];
        s += v * v;
    }
    g_sq[which][b * L3 + l] = s;
}

// ---------------- 2) 3x3 box-sum -> patch norm -------------------------------
// which==0 (img/query): store the norm.  which==1 (ref/key): store reciprocal.
__global__ void boxnorm_kernel() {
    int l = blockIdx.x * 256 + threadIdx.x;
    int b = blockIdx.y;
    int which = blockIdx.z;
    int y = l / H3, x = l % H3;
    const float* s = &g_sq[which][b * L3];
    float acc = 0.f;
    #pragma unroll
    for (int dy = -1; dy <= 1; dy++) {
        int yy = y + dy;
        if ((unsigned)yy >= H3) continue;
        #pragma unroll
        for (int dx = -1; dx <= 1; dx++) {
            int xx = x + dx;
            if ((unsigned)xx >= H3) continue;
            acc += s[yy * H3 + xx];
        }
    }
    float n = fmaxf(sqrtf(acc), EPSN);
    g_nrm[which][b * L3 + l] = (which == 1) ? (1.0f / n) : n;
}

// ---------------- 3) transpose cl_ref to channel-last ------------------------
__global__ void transpose_kernel(const float* __restrict__ src, int C, int L, int sel) {
    float* dst = (sel == 0) ? g_cl3T : (sel == 1) ? g_cl2T : g_cl1T;
    __shared__ float tile[32][33];
    int l0 = blockIdx.x * 32, c0 = blockIdx.y * 32, b = blockIdx.z;
    const float* s = src + (size_t)b * C * L;
    float* d = dst + (size_t)b * L * C;
    #pragma unroll
    for (int i = threadIdx.y; i < 32; i += 8)
        tile[i][threadIdx.x] = s[(size_t)(c0 + i) * L + l0 + threadIdx.x];
    __syncthreads();
    #pragma unroll
    for (int i = threadIdx.y; i < 32; i += 8)
        d[(size_t)(l0 + i) * C + c0 + threadIdx.x] = tile[threadIdx.x][i];
}

// ---------------- 4) SGEMM: P[b][lq][lk] = sum_c img[c][lq]*ref[c][lk] -------
// 128x128 tile, BK=16, double-buffered cp.async, 8x8 microtile, 256 threads.
__global__ void __launch_bounds__(256, 2) gemm_kernel(const float* __restrict__ img,
                                                      const float* __restrict__ ref) {
    const int b  = blockIdx.z;
    const int m0 = blockIdx.y * 128;
    const int n0 = blockIdx.x * 128;
    const float* A  = img + (size_t)b * C3 * L3;   // [k][m]
    const float* Bm = ref + (size_t)b * C3 * L3;   // [k][n]
    float* Cc = g_P + (size_t)b * L3 * L3;

    __shared__ float As[2][BK][128];
    __shared__ float Bs[2][BK][128];

    const int tid = threadIdx.x;
    const int lr  = tid >> 5;            // 0..7
    const int lc  = (tid & 31) * 4;      // 0..124
    const int tx  = tid & 15;
    const int ty  = tid >> 4;

    // global source pointers for this thread's 4 cp.async per stage
    const float* gA0 = &A [(size_t)lr       * L3 + m0 + lc];
    const float* gA1 = &A [(size_t)(lr + 8) * L3 + m0 + lc];
    const float* gB0 = &Bm[(size_t)lr       * L3 + n0 + lc];
    const float* gB1 = &Bm[(size_t)(lr + 8) * L3 + n0 + lc];
    const size_t kstep = (size_t)BK * L3;   // advance per stage

    uint32_t sA0[2], sA1[2], sB0[2], sB1[2];
    #pragma unroll
    for (int u = 0; u < 2; u++) {
        sA0[u] = (uint32_t)__cvta_generic_to_shared(&As[u][lr][lc]);
        sA1[u] = (uint32_t)__cvta_generic_to_shared(&As[u][lr + 8][lc]);
        sB0[u] = (uint32_t)__cvta_generic_to_shared(&Bs[u][lr][lc]);
        sB1[u] = (uint32_t)__cvta_generic_to_shared(&Bs[u][lr + 8][lc]);
    }

    float acc[8][8];
    #pragma unroll
    for (int i = 0; i < 8; i++)
        #pragma unroll
        for (int j = 0; j < 8; j++) acc[i][j] = 0.f;

    // prefetch stage 0
    cp_async16(sA0[0], gA0); cp_async16(sA1[0], gA1);
    cp_async16(sB0[0], gB0); cp_async16(sB1[0], gB1);
    cp_commit();

    int buf = 0;
    for (int k0 = 0; k0 < C3; k0 += BK) {
        cp_wait0();
        __syncthreads();

        if (k0 + BK < C3) {
            size_t off = (size_t)((k0 + BK) / BK) * kstep;
            int nb = buf ^ 1;
            cp_async16(sA0[nb], gA0 + off); cp_async16(sA1[nb], gA1 + off);
            cp_async16(sB0[nb], gB0 + off); cp_async16(sB1[nb], gB1 + off);
            cp_commit();
        }

        #pragma unroll
        for (int kk = 0; kk < BK; kk++) {
            float a[8], bv[8];
            *(float4*)&a[0]  = *(float4*)&As[buf][kk][ty * 4];
            *(float4*)&a[4]  = *(float4*)&As[buf][kk][64 + ty * 4];
            *(float4*)&bv[0] = *(float4*)&Bs[buf][kk][tx * 4];
            *(float4*)&bv[4] = *(float4*)&Bs[buf][kk][64 + tx * 4];
            #pragma unroll
            for (int i = 0; i < 8; i++)
                #pragma unroll
                for (int j = 0; j < 8; j++)
                    acc[i][j] += a[i] * bv[j];
        }
        buf ^= 1;
    }

    #pragma unroll
    for (int i = 0; i < 8; i++) {
        int m = m0 + ((i < 4) ? (ty * 4 + i) : (64 + ty * 4 + i - 4));
        float* row = Cc + (size_t)m * L3;
        float4 v0 = make_float4(acc[i][0], acc[i][1], acc[i][2], acc[i][3]);
        float4 v1 = make_float4(acc[i][4], acc[i][5], acc[i][6], acc[i][7]);
        *(float4*)&row[n0 + tx * 4]      = v0;
        *(float4*)&row[n0 + 64 + tx * 4] = v1;
    }
}

// ---------------- 5) shifted-sum + max/argmax over lk ------------------------
__global__ void maxarg_kernel(float* __restrict__ outS) {
    int b = blockIdx.y, lq = blockIdx.x;
    int yq = lq / H3, xq = lq % H3;
    const float* base = g_P + (size_t)b * L3 * L3;

    int  rowOff[9];
    bool qv[9];
    #pragma unroll
    for (int t = 0; t < 9; t++) {
        int di = t / 3 - 1, dj = t % 3 - 1;
        int y2 = yq + di, x2 = xq + dj;
        bool v = ((unsigned)y2 < H3) && ((unsigned)x2 < H3);
        qv[t] = v;
        int d = di * H3 + dj;
        rowOff[t] = v ? (lq + d) * L3 + d : 0;
    }
    const float* rnk = &g_nrm[1][b * L3];   // reciprocal key norms

    float best = -1e30f; int bi = 0;
    for (int lk = threadIdx.x; lk < L3; lk += 256) {
        int yk = lk / H3, xk = lk % H3;
        float s = 0.f;
        #pragma unroll
        for (int t = 0; t < 9; t++) {
            int di = t / 3 - 1, dj = t % 3 - 1;
            if (qv[t] && ((unsigned)(yk + di) < H3) && ((unsigned)(xk + dj) < H3))
                s += base[rowOff[t] + lk];
        }
        float sc = s * rnk[lk];
        if (sc > best) { best = sc; bi = lk; }
    }

    __shared__ float sv[256];
    __shared__ int   si[256];
    sv[threadIdx.x] = best; si[threadIdx.x] = bi;
    __syncthreads();
    for (int st = 128; st > 0; st >>= 1) {
        if (threadIdx.x < st) {
            float o = sv[threadIdx.x + st]; int oi = si[threadIdx.x + st];
            if (o > sv[threadIdx.x] || (o == sv[threadIdx.x] && oi < si[threadIdx.x])) {
                sv[threadIdx.x] = o; si[threadIdx.x] = oi;
            }
        }
        __syncthreads();
    }
    if (threadIdx.x == 0) {
        g_idx[b * L3 + lq] = si[0];
        outS[b * L3 + lq]  = sv[0] / g_nrm[0][b * L3 + lq];
    }
}

// ---------------- 6) fused gather + fold-normalize ---------------------------
__global__ void transfer_kernel(float* __restrict__ out, int C, int W, int s, int sel) {
    const float* clT = (sel == 0) ? g_cl3T : (sel == 1) ? g_cl2T : g_cl1T;
    __shared__ float acc[12288];                 // C*W floats == 48KB for all levels
    int b = blockIdx.y, y = blockIdx.x;
    int tid = threadIdx.x;
    int cid  = tid % C;
    int xsub = tid / C;
    int ppp  = 256 / C;                          // pixels handled in parallel

    int tyq = y / s;
    int yqs[3]; int nvy = 0;
    #pragma unroll
    for (int d = -1; d <= 1; d++) {
        int yq = tyq + d;
        if (0 <= yq && yq < H3) yqs[nvy++] = yq;
    }
    const int* idxb = g_idx + b * L3;
    size_t clb = (size_t)b * W * W * C;

    for (int x0 = 0; x0 < W; x0 += ppp) {
        int x = x0 + xsub;
        int txq = x / s;
        float sum = 0.f; int cnt = 0;
        for (int a = 0; a < nvy; a++) {
            int yq = yqs[a];
            #pragma unroll
            for (int d = -1; d <= 1; d++) {
                int xq = txq + d;
                if ((unsigned)xq >= H3) continue;
                cnt++;
                int idx = idxb[yq * H3 + xq];
                int yk = idx / H3, xk = idx % H3;
                int ys = y + s * (yk - yq);
                int xs = x + s * (xk - xq);
                if ((unsigned)ys < (unsigned)W && (unsigned)xs < (unsigned)W)
                    sum += clT[clb + ((size_t)ys * W + xs) * C + cid];
            }
        }
        acc[cid * W + x] = sum / (float)cnt;
    }
    __syncthreads();

    size_t ob = (size_t)b * C * W * W + (size_t)y * W;
    for (int i = tid; i < C * W; i += 256) {
        int c = i / W, x = i % W;
        out[ob + (size_t)c * W * W + x] = acc[i];
    }
}

// ---------------- launch ------------------------------------------------------
extern "C" void kernel_launch(void* const* d_in, const int* in_sizes, int n_in,
                              void* d_out, int out_size) {
    const float* img = (const float*)d_in[0];   // dh_img_lv3 [4,256,48,48]
    const float* ref = (const float*)d_in[1];   // dh_ref_lv3 [4,256,48,48]
    const float* cl1 = (const float*)d_in[2];   // cl_ref_lv1 [4,64,192,192]
    const float* cl2 = (const float*)d_in[3];   // cl_ref_lv2 [4,128,96,96]
    const float* cl3 = (const float*)d_in[4];   // cl_ref_lv3 [4,256,48,48]

    float* outS  = (float*)d_out;               // [4,1,48,48]
    float* outT3 = outS  + BB * L3;             // [4,256,48,48]
    float* outT2 = outT3 + (size_t)BB * C3 * L3;    // [4,128,96,96]
    float* outT1 = outT2 + (size_t)BB * C2 * L2n;   // [4,64,192,192]

    sqsum_kernel  <<<dim3(9, BB, 2), 256>>>(img, ref);
    boxnorm_kernel<<<dim3(9, BB, 2), 256>>>();

    transpose_kernel<<<dim3(L3  / 32, C3 / 32, BB), dim3(32, 8)>>>(cl3, C3, L3,  0);
    transpose_kernel<<<dim3(L2n / 32, C2 / 32, BB), dim3(32, 8)>>>(cl2, C2, L2n, 1);
    transpose_kernel<<<dim3(L1n / 32, C1 / 32, BB), dim3(32, 8)>>>(cl1, C1, L1n, 2);

    gemm_kernel<<<dim3(L3 / 128, L3 / 128, BB), 256>>>(img, ref);

    maxarg_kernel<<<dim3(L3, BB), 256>>>(outS);

    transfer_kernel<<<dim3(H3, BB), 256>>>(outT3, C3, H3, 1, 0);
    transfer_kernel<<<dim3(H2, BB), 256>>>(outT2, C2, H2, 2, 1);
    transfer_kernel<<<dim3(H1, BB), 256>>>(outT1, C1, H1, 4, 2);
}